// round 7
// baseline (speedup 1.0000x reference)
#include <cuda_runtime.h>
#include <cuda_bf16.h>
#include <math_constants.h>

#define D       32000
#define D4      8000
#define NROWS   4096
#define TA      256
#define NWARP   8
#define CHUNK4  1000            // float4s per warp chunk
#define SUBF4   125             // float4s per sub-step
#define NSUB    8
#define CAP_L   25              // per-lane bucket capacity (exp 8.35, +5.8 sigma; flagged on ovf)
#define NBIS    8
#define NNEWT   4
#define XT      1.5f            // coarse threshold (X scale); valid iff rowmaxX > XT+2 (checked)
#define CHI     0.005590169943749474f   // (1/32000)^0.5

#define WSTR    (32 * CAP_L)    // floats per warp region

__device__ float g_loss[NROWS];
__device__ int   g_done;        // zero-init; last block resets (graph-replay safe)

__device__ __forceinline__ float warp_sum(float v) {
    #pragma unroll
    for (int o = 16; o; o >>= 1) v += __shfl_xor_sync(0xffffffffu, v, o);
    return v;
}
__device__ __forceinline__ float warp_max(float v) {
    #pragma unroll
    for (int o = 16; o; o >>= 1) v = fmaxf(v, __shfl_xor_sync(0xffffffffu, v, o));
    return v;
}

#define FOR16(OP) OP(c0.x) OP(c0.y) OP(c0.z) OP(c0.w) \
                  OP(c1.x) OP(c1.y) OP(c1.z) OP(c1.w) \
                  OP(c2.x) OP(c2.y) OP(c2.z) OP(c2.w) \
                  OP(c3.x) OP(c3.y) OP(c3.z) OP(c3.w)

__global__ void __launch_bounds__(TA, 6) fused_kernel(const float* __restrict__ X,
                                                      const int*   __restrict__ target,
                                                      float*       __restrict__ out)
{
    __shared__ float s_buf[NWARP * WSTR + 128];   // per-lane buckets + overflow pad (~26 KB)
    __shared__ float s_F[2][NWARP], s_G[2][NWARP];
    __shared__ float s_p3[3][NWARP];
    __shared__ float s_max[NWARP];
    __shared__ int   s_fb;
    __shared__ int   s_last;

    const int row  = blockIdx.x;
    const int tid  = threadIdx.x;
    const int lane = tid & 31;
    const int wid  = tid >> 5;

    if (tid == 0) s_fb = 0;
    __syncthreads();

    const float4* __restrict__ Xr4 = reinterpret_cast<const float4*>(X + (size_t)row * D);
    const float*  __restrict__ Xr  = X + (size_t)row * D;
    const float4* __restrict__ W4  = Xr4 + wid * CHUNK4;

    float xt = 0.f;
    if (tid == 0) xt = Xr[target[row]];

    float* const lb = s_buf + wid * WSTR + lane * CAP_L;   // my private bucket

    // ============ single-pass filter: 3 inst/elem, no cross-lane work ======================
    const float4 FILL = make_float4(-CUDART_INF_F, -CUDART_INF_F, -CUDART_INF_F, -CUDART_INF_F);
    #define LOADSUB(dst0,dst1,dst2,dst3,sub) do {                        \
        int _b = (sub) * SUBF4;                                          \
        dst0 = W4[_b + lane];                                            \
        dst1 = W4[_b + lane + 32];                                       \
        dst2 = W4[_b + lane + 64];                                       \
        dst3 = (lane + 96 < SUBF4) ? W4[_b + lane + 96] : FILL;          \
    } while (0)

    float4 a0, a1, a2, a3, b0, b1, b2, b3;
    LOADSUB(a0, a1, a2, a3, 0);
    LOADSUB(b0, b1, b2, b3, 1);

    float* w = lb;
    #pragma unroll
    for (int sub = 0; sub < NSUB; sub++) {
        float4 c0 = a0, c1 = a1, c2 = a2, c3 = a3;
        a0 = b0; a1 = b1; a2 = b2; a3 = b3;
        if (sub + 2 < NSUB) LOADSUB(b0, b1, b2, b3, sub + 2);

        #define WR(a) { bool p = (a) > XT; if (p) *w = (a); w += (int)p; }
        FOR16(WR)
        #undef WR
    }
    #undef LOADSUB

    const int kl = (int)(w - lb);            // my candidate count (raw X scale in bucket)
    if (kl > CAP_L) s_fb = 1;                // benign race; pad absorbed the spill
    const int cl = (kl < CAP_L) ? kl : CAP_L;

    // ---- row max from candidates (row max always passes the filter when valid) ----
    {
        float mx = -CUDART_INF_F;
        for (int j = 0; j < cl; j++) mx = fmaxf(mx, lb[j]);
        mx = warp_max(mx);
        if (lane == 0) s_max[wid] = mx;      // X scale
    }
    __syncthreads();

    float rmaxX = s_max[0];
    #pragma unroll
    for (int w2 = 1; w2 < NWARP; w2++) rmaxX = fmaxf(rmaxX, s_max[w2]);
    const bool fb = (s_fb != 0) || !(rmaxX - 2.0f > XT + 1e-4f);

    if (fb) {    // rare: recompute exact row max block-wide
        __syncthreads();
        float m = -CUDART_INF_F;
        for (int i = tid; i < D; i += TA) m = fmaxf(m, Xr[i]);
        m = warp_max(m);
        if (lane == 0) s_max[wid] = m;
        __syncthreads();
        rmaxX = s_max[0];
        #pragma unroll
        for (int w2 = 1; w2 < NWARP; w2++) rmaxX = fmaxf(rmaxX, s_max[w2]);
    }
    const float rmax = 0.5f * rmaxX;         // exact: max(Xa) = 0.5*max(X)

    // ============ per-lane in-place prune to true candidates (Xa > rmax-1) ==================
    int J = 0;
    if (!fb) {
        const float tX = rmaxX - 2.0f - 1e-5f;   // X-scale; margin adds only zero-contrib elems
        int c2 = 0;
        for (int j = 0; j < cl; j++) {
            float v = lb[j];
            if (v > tX) lb[c2++] = 0.5f * v;     // Xa scale
        }
        for (int j = c2; j < CAP_L; j++) lb[j] = -1e30f;   // pad -> contributes exactly 0
        J = __reduce_max_sync(0xffffffffu, c2);  // warp-uniform trip count (typ ~7)
    }

    // ============ solve: 8 bisection + 4 safeguarded Newton =================================
    const float tau_lo0 = rmax - 1.0f;
    const float tau_hi  = rmax - CHI;
    float tau_lo = tau_lo0;
    float dm = tau_hi - tau_lo;
    float tau_m = tau_lo;
    int pb = 0;

    #pragma unroll 1
    for (int it = 0; it < NBIS + NNEWT; it++) {
        const bool newton = (it >= NBIS);
        float te;
        if (!newton) { dm *= 0.5f; te = tau_lo + dm; }
        else         { te = tau_m; }

        float F = 0.f, G = 0.f;
        if (!fb) {
            for (int j = 0; j < J; j++) {          // conflict-free: stride-25 columns
                float t = fmaxf(lb[j] - te, 0.f);
                F = fmaf(t, t, F); G += t;
            }
        } else {
            for (int i = tid; i < D; i += TA) {
                float t = fmaxf(0.5f * Xr[i] - te, 0.f);
                F = fmaf(t, t, F); G += t;
            }
        }
        #pragma unroll
        for (int o = 16; o; o >>= 1) {
            F += __shfl_xor_sync(0xffffffffu, F, o);
            G += __shfl_xor_sync(0xffffffffu, G, o);
        }
        if (lane == 0) { s_F[pb][wid] = F; s_G[pb][wid] = G; }
        __syncthreads();
        float Ft = 0.f, Gt = 0.f;
        #pragma unroll
        for (int w2 = 0; w2 < NWARP; w2++) { Ft += s_F[pb][w2]; Gt += s_G[pb][w2]; }
        const float f = Ft - 1.0f;

        if (!newton) {
            if (f >= 0.f) tau_lo = te;         // f(tau_lo) >= 0 invariant
            if (it == NBIS - 1) tau_m = tau_lo;
        } else {
            float tn = te + f / (2.0f * Gt);   // f' = -2G; Gt > 0 on bracket
            tau_m = fminf(fmaxf(tn, tau_lo0), tau_hi);
        }
        pb ^= 1;
    }

    // ============ final stats at tau_m ======================================================
    float S = 0.f, A15 = 0.f, PX = 0.f;
    if (!fb) {
        for (int j = 0; j < J; j++) {
            float v = lb[j];
            float t = fmaxf(v - tau_m, 0.f);
            float pr = t * t;
            S += pr; A15 = fmaf(pr, t, A15); PX = fmaf(pr, v, PX);
        }
    } else {
        for (int i = tid; i < D; i += TA) {
            float v = 0.5f * Xr[i];
            float t = fmaxf(v - tau_m, 0.f);
            float pr = t * t;
            S += pr; A15 = fmaf(pr, t, A15); PX = fmaf(pr, v, PX);
        }
    }
    S = warp_sum(S); A15 = warp_sum(A15); PX = warp_sum(PX);
    if (lane == 0) { s_p3[0][wid] = S; s_p3[1][wid] = A15; s_p3[2][wid] = PX; }
    __syncthreads();

    if (tid == 0) {
        float St = 0.f, At = 0.f, Pt = 0.f;
        #pragma unroll
        for (int w2 = 0; w2 < NWARP; w2++) { St += s_p3[0][w2]; At += s_p3[1][w2]; Pt += s_p3[2][w2]; }
        float sum_p15 = At / (St * sqrtf(St));
        float omega   = (1.0f - sum_p15) / 0.75f;     // alpha*(alpha-1) = 0.75
        g_loss[row] = omega + 2.0f * Pt / St - xt;

        __threadfence();
        int t = atomicAdd(&g_done, 1);
        s_last = (t == NROWS - 1);
    }
    __syncthreads();

    // ============ last block: deterministic mean ============================================
    if (s_last) {
        if (tid == 0) g_done = 0;
        __threadfence();
        float a = 0.f;
        #pragma unroll 4
        for (int i = tid; i < NROWS; i += TA) a += g_loss[i];
        a = warp_sum(a);
        if (lane == 0) s_p3[0][wid] = a;
        __syncthreads();
        if (tid == 0) {
            float tot = 0.f;
            #pragma unroll
            for (int w2 = 0; w2 < NWARP; w2++) tot += s_p3[0][w2];
            out[0] = tot / (float)NROWS;
        }
    }
}

// ============================================================================
extern "C" void kernel_launch(void* const* d_in, const int* in_sizes, int n_in,
                              void* d_out, int out_size)
{
    const float* X      = (const float*)d_in[0];
    const int*   target = (const int*)  d_in[1];
    float*       out    = (float*)d_out;

    fused_kernel<<<NROWS, TA>>>(X, target, out);
}